// round 2
// baseline (speedup 1.0000x reference)
#include <cuda_runtime.h>
#include <cuda_bf16.h>

// Problem constants
#define B   16
#define NQ  512
#define NK  1024
#define CIN 128         // CQ == CV == 128
#define H   8
#define D   64
#define HD  (H * D)     // 512

// Scratch: Q/K/V in [b][h][row][d] layout (attention-friendly, contiguous per (b,h))
__device__ float g_Q[B * H * NQ * D];   // 16 MB
__device__ float g_K[B * H * NK * D];   // 32 MB
__device__ float g_V[B * H * NK * D];   // 32 MB

// ---------------------------------------------------------------------------
// Projection: Y[b][h][row][d] = (sum_c X[row_glob][c] * W[c][h*64+d] + bias) * scale
// Block: 128 threads, handles 8 rows x all 512 output cols (4 cols/thread).
// X tile staged in smem; W read as float4 (L2-resident, 256 KB).
// ---------------------------------------------------------------------------
__global__ __launch_bounds__(128)
void proj_kernel(const float* __restrict__ X, const float* __restrict__ W,
                 const float* __restrict__ bias, int which, int Nrows, float scale)
{
    float* __restrict__ Y = (which == 0) ? g_Q : (which == 1) ? g_K : g_V;

    __shared__ float xs[8][128];
    const int tid  = threadIdx.x;
    const long row0 = (long)blockIdx.x * 8;

    // load 8 input rows (8*128 floats, 8 per thread, coalesced)
    #pragma unroll
    for (int r = 0; r < 8; r++)
        xs[r][tid] = X[(row0 + r) * CIN + tid];
    __syncthreads();

    float4 acc[8];
    #pragma unroll
    for (int r = 0; r < 8; r++) acc[r] = make_float4(0.f, 0.f, 0.f, 0.f);

    const float4* __restrict__ W4 = (const float4*)W;   // [c][128 groups]
    #pragma unroll 4
    for (int c = 0; c < CIN; c++) {
        float4 w = __ldg(&W4[c * 128 + tid]);
        #pragma unroll
        for (int r = 0; r < 8; r++) {
            float x = xs[r][c];
            acc[r].x += x * w.x;
            acc[r].y += x * w.y;
            acc[r].z += x * w.z;
            acc[r].w += x * w.w;
        }
    }

    const float4 b4 = __ldg(&((const float4*)bias)[tid]);
    const int n = tid * 4;          // output col group
    const int h = n >> 6;           // head
    const int d = n & 63;           // dim within head (multiple of 4)

    #pragma unroll
    for (int r = 0; r < 8; r++) {
        long row = row0 + r;
        int  b   = (int)(row / Nrows);
        int  lr  = (int)(row % Nrows);
        float4 o;
        o.x = (acc[r].x + b4.x) * scale;
        o.y = (acc[r].y + b4.y) * scale;
        o.z = (acc[r].z + b4.z) * scale;
        o.w = (acc[r].w + b4.w) * scale;
        ((float4*)Y)[((long)(b * H + h) * Nrows + lr) * (D / 4) + (d >> 2)] = o;
    }
}

// ---------------------------------------------------------------------------
// Fused masked attention. Grid (NQ/128, H, B), 128 threads.
// One thread owns one query row: q[64] + acc[64] in registers.
// K/V staged in smem in 64-key tiles. No max-tracking needed: scores are
// tiny (|s| << 80) and masked scores are s - 1e5 -> expf underflows to 0,
// exactly matching the reference softmax.
// ---------------------------------------------------------------------------
#define TK 64

__global__ __launch_bounds__(128)
void attn_kernel(const float* __restrict__ c_mask, float* __restrict__ out)
{
    __shared__ float4 Ks[TK * (D / 4)];   // 16 KB
    __shared__ float4 Vs[TK * (D / 4)];   // 16 KB
    __shared__ float  ms[TK];

    const int tid = threadIdx.x;
    const int h   = blockIdx.y;
    const int b   = blockIdx.z;
    const int qi  = blockIdx.x * 128 + tid;

    const long bh = (long)b * H + h;

    // q row into registers (pre-scaled by 1/sqrt(D) in projection)
    float4 q[16];
    {
        const float4* qp = (const float4*)&g_Q[(bh * NQ + qi) * D];
        #pragma unroll
        for (int i = 0; i < 16; i++) q[i] = qp[i];
    }

    float4 acc[16];
    #pragma unroll
    for (int i = 0; i < 16; i++) acc[i] = make_float4(0.f, 0.f, 0.f, 0.f);
    float l = 0.f;

    const float4* __restrict__ Kb = (const float4*)&g_K[bh * NK * D];
    const float4* __restrict__ Vb = (const float4*)&g_V[bh * NK * D];
    const float*  __restrict__ mb = c_mask + (long)b * NK;

    for (int kt = 0; kt < NK / TK; kt++) {
        __syncthreads();   // previous tile fully consumed
        // stage K/V tile: TK*16 float4 each, 8 per thread, coalesced
        #pragma unroll
        for (int i = 0; i < 8; i++) {
            Ks[tid + i * 128] = Kb[kt * (TK * 16) + tid + i * 128];
            Vs[tid + i * 128] = Vb[kt * (TK * 16) + tid + i * 128];
        }
        if (tid < TK) ms[tid] = -100000.f * (1.f - mb[kt * TK + tid]);
        __syncthreads();

        #pragma unroll 1
        for (int j = 0; j < TK; j++) {
            float s0 = 0.f, s1 = 0.f, s2 = 0.f, s3 = 0.f;
            #pragma unroll
            for (int i = 0; i < 16; i++) {
                float4 k = Ks[j * 16 + i];      // broadcast LDS.128
                s0 += q[i].x * k.x;
                s1 += q[i].y * k.y;
                s2 += q[i].z * k.z;
                s3 += q[i].w * k.w;
            }
            float s = (s0 + s1) + (s2 + s3) + ms[j];
            float p = __expf(s);                // 0 exactly for masked keys
            l += p;
            #pragma unroll
            for (int i = 0; i < 16; i++) {
                float4 v = Vs[j * 16 + i];      // broadcast LDS.128
                acc[i].x += p * v.x;
                acc[i].y += p * v.y;
                acc[i].z += p * v.z;
                acc[i].w += p * v.w;
            }
        }
    }

    const float inv = 1.f / l;
    float4* op = (float4*)&out[((long)b * NQ + qi) * HD + h * D];
    #pragma unroll
    for (int i = 0; i < 16; i++) {
        float4 o;
        o.x = acc[i].x * inv;
        o.y = acc[i].y * inv;
        o.z = acc[i].z * inv;
        o.w = acc[i].w * inv;
        op[i] = o;
    }
}

// ---------------------------------------------------------------------------
// kernel_launch: 3 projection launches + fused attention. Graph-capturable:
// launches only, no sync, no alloc.
// ---------------------------------------------------------------------------
extern "C" void kernel_launch(void* const* d_in, const int* in_sizes, int n_in,
                              void* d_out, int out_size)
{
    const float* query  = (const float*)d_in[0];
    const float* key    = (const float*)d_in[1];
    const float* c_mask = (const float*)d_in[2];
    const float* Wq     = (const float*)d_in[3];
    const float* bq     = (const float*)d_in[4];
    const float* Wk     = (const float*)d_in[5];
    const float* bk     = (const float*)d_in[6];
    const float* Wv     = (const float*)d_in[7];
    const float* bv     = (const float*)d_in[8];
    float* out = (float*)d_out;

    const float qscale = 0.125f;   // 1/sqrt(D), folded into Q projection

    // Q: M = B*NQ = 8192 rows -> 1024 blocks
    proj_kernel<<<(B * NQ) / 8, 128>>>(query, Wq, bq, 0, NQ, qscale);
    // K: M = B*NK = 16384 rows -> 2048 blocks
    proj_kernel<<<(B * NK) / 8, 128>>>(key,   Wk, bk, 1, NK, 1.0f);
    // V
    proj_kernel<<<(B * NK) / 8, 128>>>(key,   Wv, bv, 2, NK, 1.0f);

    // Attention: grid (NQ/128, H, B) = (4, 8, 16) = 512 blocks
    dim3 grid(NQ / 128, H, B);
    attn_kernel<<<grid, 128>>>(c_mask, out);
}

// round 4
// speedup vs baseline: 1.2111x; 1.2111x over previous
#include <cuda_runtime.h>
#include <cuda_bf16.h>

#define B   16
#define NQ  512
#define NK  1024
#define CIN 128
#define H   8
#define D   64
#define HD  (H * D)

// Scratch: Q/K/V in [b][h][row][d] layout
__device__ float g_Q[B * H * NQ * D];
__device__ float g_K[B * H * NK * D];
__device__ float g_V[B * H * NK * D];

typedef unsigned long long u64;

// ---- packed f32x2 helpers (sm_103a FFMA2 path, ptxas won't auto-fuse) ----
__device__ __forceinline__ u64 pk2(float a) {
    u64 r; asm("mov.b64 %0,{%1,%1};" : "=l"(r) : "f"(a)); return r;
}
__device__ __forceinline__ void fma2(u64& d, u64 a, u64 b) {
    asm("fma.rn.f32x2 %0,%1,%2,%0;" : "+l"(d) : "l"(a), "l"(b));
}
__device__ __forceinline__ u64 add2(u64 a, u64 b) {
    u64 r; asm("add.rn.f32x2 %0,%1,%2;" : "=l"(r) : "l"(a), "l"(b)); return r;
}
__device__ __forceinline__ float2 upk(u64 v) {
    float lo, hi; asm("mov.b64 {%0,%1},%2;" : "=f"(lo), "=f"(hi) : "l"(v));
    return make_float2(lo, hi);
}

// ---------------------------------------------------------------------------
// Projection with FFMA2: Y[b][h][row][d] = (X @ W + bias) * scale
// ---------------------------------------------------------------------------
__global__ __launch_bounds__(128)
void proj_kernel(const float* __restrict__ X, const float* __restrict__ W,
                 const float* __restrict__ bias, int which, int Nrows, float scale)
{
    float* __restrict__ Y = (which == 0) ? g_Q : (which == 1) ? g_K : g_V;

    __shared__ float xs[8][128];
    const int tid = threadIdx.x;
    const long row0 = (long)blockIdx.x * 8;

    #pragma unroll
    for (int r = 0; r < 8; r++)
        xs[r][tid] = X[(row0 + r) * CIN + tid];
    __syncthreads();

    u64 acc2[8][2];
    #pragma unroll
    for (int r = 0; r < 8; r++) { acc2[r][0] = 0ull; acc2[r][1] = 0ull; }

    const ulonglong2* __restrict__ W2 = (const ulonglong2*)W;  // [c][128 groups of 4]
    #pragma unroll 4
    for (int c = 0; c < CIN; c++) {
        ulonglong2 wv = W2[c * 128 + tid];
        #pragma unroll
        for (int r = 0; r < 8; r++) {
            u64 xx = pk2(xs[r][c]);
            fma2(acc2[r][0], xx, wv.x);
            fma2(acc2[r][1], xx, wv.y);
        }
    }

    const float4 b4 = ((const float4*)bias)[tid];
    const int n = tid * 4;
    const int h = n >> 6;
    const int d = n & 63;

    #pragma unroll
    for (int r = 0; r < 8; r++) {
        long row = row0 + r;
        int  b   = (int)(row / Nrows);
        int  lr  = (int)(row % Nrows);
        float2 lo = upk(acc2[r][0]);
        float2 hi = upk(acc2[r][1]);
        float4 o;
        o.x = (lo.x + b4.x) * scale;
        o.y = (lo.y + b4.y) * scale;
        o.z = (hi.x + b4.z) * scale;
        o.w = (hi.y + b4.w) * scale;
        ((float4*)Y)[((long)(b * H + h) * Nrows + lr) * (D / 4) + (d >> 2)] = o;
    }
}

// ---------------------------------------------------------------------------
// Fused attention as two register-tiled GEMMs per 64-key tile.
// Block: 128 threads = (ty 0..15) x (tx 0..7). 128 queries per block.
// Phase A: S[128x64] = Q·K^T, 8q x 8k micro-tile/thread, keys packed f32x2.
// exp (no max-tracking: scores tiny, masked -> exact 0), P -> smem [k][q].
// Phase B: O[128x64] += P·V, 8q x 8d micro-tile/thread, dims packed f32x2.
// ---------------------------------------------------------------------------
#define ATTN_SMEM ((64*128 + 64*64 + 64*64 + 64*128 + 64) * 4)

__global__ __launch_bounds__(128, 2)
void attn_kernel(const float* __restrict__ c_mask, float* __restrict__ out)
{
    extern __shared__ float sm[];
    float* Qs = sm;                 // [d][q]  64 x 128
    float* Ks = Qs + 64 * 128;      // [d][k]  64 x 64
    float* Vs = Ks + 64 * 64;       // [k][d]  64 x 64
    float* Ps = Vs + 64 * 64;       // [k][q]  64 x 128
    float* ms = Ps + 64 * 128;      // [k]     64

    const int tid = threadIdx.x;
    const int ty  = tid >> 3;       // 0..15 -> query group
    const int tx  = tid & 7;        // 0..7  -> key/dim group
    const int h   = blockIdx.y;
    const int b   = blockIdx.z;
    const long bh = (long)b * H + h;
    const int q0  = blockIdx.x * 128;

    // Load Q tile transposed: Qs[d][q], one query row per thread (conflict-free STS.32)
    {
        const float4* qg = (const float4*)&g_Q[(bh * NQ + q0 + tid) * D];
        #pragma unroll
        for (int c4 = 0; c4 < 16; c4++) {
            float4 v = qg[c4];
            int c = c4 * 4;
            Qs[(c + 0) * 128 + tid] = v.x;
            Qs[(c + 1) * 128 + tid] = v.y;
            Qs[(c + 2) * 128 + tid] = v.z;
            Qs[(c + 3) * 128 + tid] = v.w;
        }
    }

    u64 o2[8][4];
    float lsum[8];
    #pragma unroll
    for (int i = 0; i < 8; i++) {
        lsum[i] = 0.f;
        #pragma unroll
        for (int p = 0; p < 4; p++) o2[i][p] = 0ull;
    }

    const float* __restrict__ mb = c_mask + (long)b * NK;
    const float4* Qs4 = (const float4*)Qs;
    const ulonglong2* Ks2 = (const ulonglong2*)Ks;
    const ulonglong2* Vs2 = (const ulonglong2*)Vs;
    float4* Ps4 = (float4*)Ps;

    #pragma unroll 1
    for (int kt = 0; kt < NK / 64; kt++) {
        __syncthreads();   // prev tile's phase B done with Ks/Vs/Ps

        // Stage K transposed [d][k]: 2 threads per key row, 32 dims each
        {
            int k = tid & 63, half = tid >> 6;
            const float4* kg = (const float4*)&g_K[(bh * NK + kt * 64 + k) * D];
            #pragma unroll
            for (int c4 = 0; c4 < 8; c4++) {
                float4 v = kg[half * 8 + c4];
                int c = half * 32 + c4 * 4;
                Ks[(c + 0) * 64 + k] = v.x;
                Ks[(c + 1) * 64 + k] = v.y;
                Ks[(c + 2) * 64 + k] = v.z;
                Ks[(c + 3) * 64 + k] = v.w;
            }
        }
        // Stage V natural [k][d], coalesced float4 copy
        {
            const float4* vg = (const float4*)&g_V[(bh * NK + (long)kt * 64) * D];
            float4* Vs4 = (float4*)Vs;
            #pragma unroll
            for (int i = 0; i < 8; i++)
                Vs4[tid + i * 128] = vg[tid + i * 128];
        }
        if (tid < 64) ms[tid] = -100000.f * (1.f - mb[kt * 64 + tid]);
        __syncthreads();

        // ---- Phase A: S = Q·K^T, accumulate key-pairs in f32x2 ----
        u64 s2[8][4];
        #pragma unroll
        for (int i = 0; i < 8; i++)
            #pragma unroll
            for (int p = 0; p < 4; p++) s2[i][p] = 0ull;

        #pragma unroll 2
        for (int c = 0; c < 64; c++) {
            float4 qa = Qs4[c * 32 + ty * 2];
            float4 qb = Qs4[c * 32 + ty * 2 + 1];
            ulonglong2 ka = Ks2[c * 16 + tx * 2];       // keys tx*8 .. +3
            ulonglong2 kb = Ks2[c * 16 + tx * 2 + 1];   // keys tx*8+4 .. +7
            float qf[8] = {qa.x, qa.y, qa.z, qa.w, qb.x, qb.y, qb.z, qb.w};
            #pragma unroll
            for (int i = 0; i < 8; i++) {
                u64 qq = pk2(qf[i]);
                fma2(s2[i][0], qq, ka.x);
                fma2(s2[i][1], qq, ka.y);
                fma2(s2[i][2], qq, kb.x);
                fma2(s2[i][3], qq, kb.y);
            }
        }

        // mask + exp + row-sum (bfly over the 8 tx lanes) + P store
        ulonglong2 m01 = ((const ulonglong2*)ms)[tx * 2];
        ulonglong2 m23 = ((const ulonglong2*)ms)[tx * 2 + 1];
        float p[8][8];
        #pragma unroll
        for (int i = 0; i < 8; i++) {
            float2 e0 = upk(add2(s2[i][0], m01.x));
            float2 e1 = upk(add2(s2[i][1], m01.y));
            float2 e2 = upk(add2(s2[i][2], m23.x));
            float2 e3 = upk(add2(s2[i][3], m23.y));
            p[i][0] = __expf(e0.x); p[i][1] = __expf(e0.y);
            p[i][2] = __expf(e1.x); p[i][3] = __expf(e1.y);
            p[i][4] = __expf(e2.x); p[i][5] = __expf(e2.y);
            p[i][6] = __expf(e3.x); p[i][7] = __expf(e3.y);
            float r = ((p[i][0] + p[i][1]) + (p[i][2] + p[i][3]))
                    + ((p[i][4] + p[i][5]) + (p[i][6] + p[i][7]));
            r += __shfl_xor_sync(0xffffffffu, r, 1);
            r += __shfl_xor_sync(0xffffffffu, r, 2);
            r += __shfl_xor_sync(0xffffffffu, r, 4);
            lsum[i] += r;
        }
        #pragma unroll
        for (int j = 0; j < 8; j++) {
            Ps4[(tx * 8 + j) * 32 + ty * 2]     = make_float4(p[0][j], p[1][j], p[2][j], p[3][j]);
            Ps4[(tx * 8 + j) * 32 + ty * 2 + 1] = make_float4(p[4][j], p[5][j], p[6][j], p[7][j]);
        }
        __syncthreads();

        // ---- Phase B: O += P·V, accumulate dim-pairs in f32x2 ----
        #pragma unroll 2
        for (int j = 0; j < 64; j++) {
            float4 pa = Ps4[j * 32 + ty * 2];
            float4 pb = Ps4[j * 32 + ty * 2 + 1];
            ulonglong2 va = Vs2[j * 16 + tx * 2];       // dims tx*8 .. +3
            ulonglong2 vb = Vs2[j * 16 + tx * 2 + 1];
            float pf[8] = {pa.x, pa.y, pa.z, pa.w, pb.x, pb.y, pb.z, pb.w};
            #pragma unroll
            for (int i = 0; i < 8; i++) {
                u64 pp = pk2(pf[i]);
                fma2(o2[i][0], pp, va.x);
                fma2(o2[i][1], pp, va.y);
                fma2(o2[i][2], pp, vb.x);
                fma2(o2[i][3], pp, vb.y);
            }
        }
    }

    // Epilogue: normalize and write out[b][q][h*64 + d]
    #pragma unroll
    for (int i = 0; i < 8; i++) {
        float inv = 1.f / lsum[i];
        float2 a0 = upk(o2[i][0]);
        float2 a1 = upk(o2[i][1]);
        float2 a2 = upk(o2[i][2]);
        float2 a3 = upk(o2[i][3]);
        int q = q0 + ty * 8 + i;
        float4* op = (float4*)&out[((long)b * NQ + q) * HD + h * D + tx * 8];
        op[0] = make_float4(a0.x * inv, a0.y * inv, a1.x * inv, a1.y * inv);
        op[1] = make_float4(a2.x * inv, a2.y * inv, a3.x * inv, a3.y * inv);
    }
}

// ---------------------------------------------------------------------------
extern "C" void kernel_launch(void* const* d_in, const int* in_sizes, int n_in,
                              void* d_out, int out_size)
{
    const float* query  = (const float*)d_in[0];
    const float* key    = (const float*)d_in[1];
    const float* c_mask = (const float*)d_in[2];
    const float* Wq     = (const float*)d_in[3];
    const float* bq     = (const float*)d_in[4];
    const float* Wk     = (const float*)d_in[5];
    const float* bk     = (const float*)d_in[6];
    const float* Wv     = (const float*)d_in[7];
    const float* bv     = (const float*)d_in[8];
    float* out = (float*)d_out;

    cudaFuncSetAttribute(attn_kernel, cudaFuncAttributeMaxDynamicSharedMemorySize, ATTN_SMEM);

    const float qscale = 0.125f;   // 1/sqrt(D) folded into Q projection

    proj_kernel<<<(B * NQ) / 8, 128>>>(query, Wq, bq, 0, NQ, qscale);
    proj_kernel<<<(B * NK) / 8, 128>>>(key,   Wk, bk, 1, NK, 1.0f);
    proj_kernel<<<(B * NK) / 8, 128>>>(key,   Wv, bv, 2, NK, 1.0f);

    dim3 grid(NQ / 128, H, B);
    attn_kernel<<<grid, 128, ATTN_SMEM>>>(c_mask, out);
}